// round 6
// baseline (speedup 1.0000x reference)
#include <cuda_runtime.h>

#define N_MAXN 100000
#define E_MAXE 3200000
#define HID 16
#define NC 40
#define F_IN 256
#define SCAN_B 256

// Scratch (device globals -- no allocation allowed)
__device__ int   d_is64;                 // 1 if edge_index words are int64 pairs
__device__ int   d_cnt[N_MAXN];          // in-degree (excluding self-loop)
__device__ int   d_rowstart[N_MAXN];     // CSR row offsets
__device__ int   d_cursor[N_MAXN];       // fill cursors
__device__ int   d_perm[E_MAXE];         // src node per edge, sorted by dst
__device__ int   d_bsum[1024];           // scan block sums
__device__ float d_dinv[N_MAXN];
__device__ __align__(16) float d_gA[N_MAXN * HID];  // dinv*(x@W1)
__device__ __align__(16) float d_gB[N_MAXN * HID];  // dinv*relu(...)
__device__ __align__(16) float d_agg[N_MAXN * HID]; // layer-2 aggregate

// ---- edge_index layout detection: int64 (odd words all 0) vs int32 ----
__global__ void k_detect(const int* __restrict__ w, int nwords) {
    __shared__ int anynz;
    if (threadIdx.x == 0) anynz = 0;
    __syncthreads();
    int limit = nwords < 8192 ? nwords : 8192;
    for (int i = threadIdx.x * 2 + 1; i < limit; i += 512)
        if (w[i] != 0) anynz = 1;
    __syncthreads();
    if (threadIdx.x == 0) d_is64 = anynz ? 0 : 1;
}

__device__ __forceinline__ int clampi(int v, int n) {
    return v < 0 ? 0 : (v >= n ? n - 1 : v);
}

__global__ void k_zero(int n) {
    int i = blockIdx.x * blockDim.x + threadIdx.x;
    if (i < n) d_cnt[i] = 0;
}

__global__ void k_hist(const int* __restrict__ w, int E, int n) {
    int e = blockIdx.x * blockDim.x + threadIdx.x;
    if (e >= E) return;
    int is64 = d_is64;
    int d = is64 ? w[2 * (E + e)] : w[E + e];
    atomicAdd(&d_cnt[clampi(d, n)], 1);
}

// Block-local exclusive scan of d_cnt -> d_rowstart, block totals -> d_bsum
__global__ void k_scan1(int n) {
    __shared__ int s[SCAN_B];
    int i = blockIdx.x * SCAN_B + threadIdx.x;
    int v = (i < n) ? d_cnt[i] : 0;
    s[threadIdx.x] = v;
    __syncthreads();
    for (int off = 1; off < SCAN_B; off <<= 1) {
        int t = (threadIdx.x >= off) ? s[threadIdx.x - off] : 0;
        __syncthreads();
        s[threadIdx.x] += t;
        __syncthreads();
    }
    if (i < n) d_rowstart[i] = s[threadIdx.x] - v;
    if (threadIdx.x == SCAN_B - 1) d_bsum[blockIdx.x] = s[SCAN_B - 1];
}

__global__ void k_scan2(int nb) {
    __shared__ int s[1024];
    int t = threadIdx.x;
    int v = (t < nb) ? d_bsum[t] : 0;
    s[t] = v;
    __syncthreads();
    for (int off = 1; off < 1024; off <<= 1) {
        int u = (t >= off) ? s[t - off] : 0;
        __syncthreads();
        s[t] += u;
        __syncthreads();
    }
    if (t < nb) d_bsum[t] = s[t] - v;
}

__global__ void k_scan3(int n) {
    int i = blockIdx.x * blockDim.x + threadIdx.x;
    if (i < n) {
        int start = d_rowstart[i] + d_bsum[i / SCAN_B];
        d_rowstart[i] = start;
        d_cursor[i] = start;
        d_dinv[i] = rsqrtf((float)d_cnt[i] + 1.0f);
    }
}

__global__ void k_fill(const int* __restrict__ w, int E, int n) {
    int e = blockIdx.x * blockDim.x + threadIdx.x;
    if (e >= E) return;
    int is64 = d_is64;
    int s = is64 ? w[2 * e] : w[e];
    int d = is64 ? w[2 * (E + e)] : w[E + e];
    int pos = atomicAdd(&d_cursor[clampi(d, n)], 1);
    d_perm[pos] = clampi(s, n);
}

// GEMM1: gA[i] = dinv[i] * (x[i] @ W1). 128 rows/block, 128 threads.
__global__ void k_gemm1(const float* __restrict__ x, const float* __restrict__ W1, int n) {
    __shared__ float W1s[F_IN * HID];   // 16 KB
    __shared__ float xs[128 * 33];      // padded
    int tid = threadIdx.x;
    for (int i = tid; i < F_IN * HID; i += 128) W1s[i] = W1[i];
    int row0 = blockIdx.x * 128;

    float acc[HID];
#pragma unroll
    for (int j = 0; j < HID; j++) acc[j] = 0.f;

    for (int kc = 0; kc < F_IN; kc += 32) {
        __syncthreads();
#pragma unroll
        for (int i = 0; i < 32; i++) {
            int lin = tid + 128 * i;
            int r = lin >> 5, k = lin & 31;
            int row = row0 + r;
            xs[r * 33 + k] = (row < n) ? x[(long long)row * F_IN + kc + k] : 0.f;
        }
        __syncthreads();
#pragma unroll
        for (int k = 0; k < 32; k++) {
            float xv = xs[tid * 33 + k];
            const float* w = &W1s[(kc + k) * HID];
#pragma unroll
            for (int j = 0; j < HID; j++) acc[j] = fmaf(xv, w[j], acc[j]);
        }
    }

    int row = row0 + tid;
    if (row < n) {
        float di = d_dinv[row];
        float4* g = (float4*)&d_gA[row * HID];
#pragma unroll
        for (int q = 0; q < 4; q++)
            g[q] = make_float4(di * acc[q * 4 + 0], di * acc[q * 4 + 1],
                               di * acc[q * 4 + 2], di * acc[q * 4 + 3]);
    }
}

// CSR gather. 4 threads per node (one float4 quad each, same warp -> perm broadcast).
// layer 0: reads gA, writes gB = dinv * relu(dinv*acc + b1)
// layer 1: reads gB, writes agg = acc (raw)
__global__ void k_gather(const float* __restrict__ b1, int n, int layer) {
    int idx = blockIdx.x * blockDim.x + threadIdx.x;
    if (idx >= n * 4) return;
    int node = idx >> 2, q = idx & 3;
    const float4* __restrict__ g4 = (const float4*)(layer ? d_gB : d_gA);

    float4 acc = g4[node * 4 + q];  // self-loop term
    int start = d_rowstart[node];
    int end = start + d_cnt[node];
#pragma unroll 4
    for (int j = start; j < end; j++) {
        int s = d_perm[j];
        float4 v = g4[s * 4 + q];
        acc.x += v.x; acc.y += v.y; acc.z += v.z; acc.w += v.w;
    }

    float di = d_dinv[node];
    if (layer == 0) {
        float b0 = b1[q * 4 + 0], bb1 = b1[q * 4 + 1];
        float b2v = b1[q * 4 + 2], b3 = b1[q * 4 + 3];
        float4 h;
        h.x = di * fmaxf(fmaf(di, acc.x, b0), 0.f);
        h.y = di * fmaxf(fmaf(di, acc.y, bb1), 0.f);
        h.z = di * fmaxf(fmaf(di, acc.z, b2v), 0.f);
        h.w = di * fmaxf(fmaf(di, acc.w, b3), 0.f);
        ((float4*)d_gB)[idx] = h;
    } else {
        ((float4*)d_agg)[idx] = acc;
    }
}

// Final: logits = (dinv*agg) @ W2 + b2; log_softmax. One thread per node.
__global__ void k_final(const float* __restrict__ W2, const float* __restrict__ b2,
                        float* __restrict__ out, int n) {
    __shared__ float W2s[HID * NC];
    __shared__ float b2s[NC];
    int tid = threadIdx.x;
    for (int i = tid; i < HID * NC; i += blockDim.x) W2s[i] = W2[i];
    if (tid < NC) b2s[tid] = b2[tid];
    __syncthreads();

    int i = blockIdx.x * blockDim.x + tid;
    if (i >= n) return;
    float di = d_dinv[i];
    float p[HID];
#pragma unroll
    for (int q = 0; q < 4; q++) {
        float4 v = ((const float4*)d_agg)[i * 4 + q];
        p[q * 4 + 0] = di * v.x;
        p[q * 4 + 1] = di * v.y;
        p[q * 4 + 2] = di * v.z;
        p[q * 4 + 3] = di * v.w;
    }
    float l[NC];
#pragma unroll
    for (int j = 0; j < NC; j++) l[j] = b2s[j];
#pragma unroll
    for (int k = 0; k < HID; k++) {
        float pk = p[k];
#pragma unroll
        for (int j = 0; j < NC; j++) l[j] = fmaf(pk, W2s[k * NC + j], l[j]);
    }
    float m = l[0];
#pragma unroll
    for (int j = 1; j < NC; j++) m = fmaxf(m, l[j]);
    float sum = 0.f;
#pragma unroll
    for (int j = 0; j < NC; j++) sum += __expf(l[j] - m);
    float lse = m + __logf(sum);
#pragma unroll
    for (int j = 0; j < NC; j++) out[(long long)i * NC + j] = l[j] - lse;
}

extern "C" void kernel_launch(void* const* d_in, const int* in_sizes, int n_in,
                              void* d_out, int out_size) {
    const float* x   = (const float*)d_in[0];
    const int*   eiw = (const int*)d_in[1];   // raw 32-bit words; layout detected on device
    const float* W1  = (const float*)d_in[2];
    const float* b1  = (const float*)d_in[3];
    const float* W2  = (const float*)d_in[4];
    const float* b2  = (const float*)d_in[5];
    float* out = (float*)d_out;

    int n = in_sizes[0] / F_IN;        // 100000
    int E = in_sizes[1] / 2;           // 3200000 (element count identical for i32/i64)
    int nwords = in_sizes[1] * 2;      // if int64-backed; detection only reads first 8192
    int nb = (n + SCAN_B - 1) / SCAN_B;

    k_detect<<<1, 256>>>(eiw, nwords);
    k_zero  <<<(n + 255) / 256, 256>>>(n);
    k_hist  <<<(E + 255) / 256, 256>>>(eiw, E, n);
    k_scan1 <<<nb, SCAN_B>>>(n);
    k_scan2 <<<1, 1024>>>(nb);
    k_scan3 <<<(n + 255) / 256, 256>>>(n);
    k_fill  <<<(E + 255) / 256, 256>>>(eiw, E, n);

    k_gemm1 <<<(n + 127) / 128, 128>>>(x, W1, n);
    k_gather<<<(n * 4 + 255) / 256, 256>>>(b1, n, 0);
    k_gather<<<(n * 4 + 255) / 256, 256>>>(b1, n, 1);
    k_final <<<(n + 127) / 128, 128>>>(W2, b2, out, n);
}